// round 9
// baseline (speedup 1.0000x reference)
#include <cuda_runtime.h>
#include <cstddef>
#include <cstdint>

#define N_NODES 50000
#define C_DIM   64
#define HID_DIM 128
#define R_DIM   16
#define B_DIM   2
#define L_DIM   12
#define E_EDGES 1600000
#define T_DIM   8
#define M_ROWS  (B_DIM * N_NODES)   // 100000

// Tables laid out [node][batch][16 floats]: one node = one 128B line.
__device__ __align__(128) float4 g_a[M_ROWS * 4];
__device__ __align__(128) float4 g_b[M_ROWS * 4];

__device__ __forceinline__ uint32_t f2tf(float x) {
    uint32_t r;
    asm("cvt.rna.tf32.f32 %0, %1;" : "=r"(r) : "f"(x));
    return r;
}

__device__ __forceinline__ void mma_tf32(float* d, uint32_t a0, uint32_t a1,
                                         uint32_t a2, uint32_t a3,
                                         uint32_t b0, uint32_t b1) {
    asm volatile(
        "mma.sync.aligned.m16n8k8.row.col.f32.tf32.tf32.f32 "
        "{%0,%1,%2,%3}, {%4,%5,%6,%7}, {%8,%9}, {%0,%1,%2,%3};"
        : "+f"(d[0]), "+f"(d[1]), "+f"(d[2]), "+f"(d[3])
        : "r"(a0), "r"(a1), "r"(a2), "r"(a3), "r"(b0), "r"(b1));
}

// ---------------------------------------------------------------------------
// Kernel 1: tf32 tensor-core MLP (unchanged from measured ~47us version).
// ---------------------------------------------------------------------------
#define SH  68
#define SW1 136
#define SHD 132
#define SW2 20

__global__ __launch_bounds__(256, 2)
void mlp_kernel(const float* __restrict__ X,
                const float* __restrict__ W1s, const float* __restrict__ b1s,
                const float* __restrict__ W2s, const float* __restrict__ b2s,
                const float* __restrict__ W1d, const float* __restrict__ b1d,
                const float* __restrict__ W2d, const float* __restrict__ b2d)
{
    extern __shared__ float sh[];
    float* W2sm = sh;                     // [128][20]
    float* Hsm  = sh + 128 * SW2;         // [128][68]
    float* W1sm = Hsm + 128 * SH;         // [64][136]
    float* Hid  = Hsm;                    // [128][132] alias

    const int tid  = threadIdx.x;
    const int lane = tid & 31;
    const int warp = tid >> 5;
    const int g    = lane >> 2;
    const int t    = lane & 3;
    const int m0   = blockIdx.x * 128;

    uint32_t* Hu  = (uint32_t*)Hsm;
    uint32_t* W1u = (uint32_t*)W1sm;
    uint32_t* W2u = (uint32_t*)W2sm;
    uint32_t* Du  = (uint32_t*)Hid;

    for (int set = 0; set < 2; set++) {
        const float* W1 = set ? W1d : W1s;
        const float* b1 = set ? b1d : b1s;
        const float* W2 = set ? W2d : W2s;
        const float* b2 = set ? b2d : b2s;
        float4* outTab  = set ? g_b : g_a;

        #pragma unroll
        for (int u = 0; u < 8; u++) {
            int id = tid + 256 * u;
            int r  = id >> 4, cg = id & 15;
            int m  = m0 + r;
            float4 v = make_float4(0.f, 0.f, 0.f, 0.f);
            if (m < M_ROWS) {
                int b = m / N_NODES;
                int n = m - b * N_NODES;
                v = *(const float4*)&X[(((size_t)b * T_DIM + (T_DIM - 1)) * N_NODES + n) * C_DIM + cg * 4];
            }
            uint4 w; w.x = f2tf(v.x); w.y = f2tf(v.y); w.z = f2tf(v.z); w.w = f2tf(v.w);
            *(uint4*)&Hu[r * SH + cg * 4] = w;
        }
        #pragma unroll
        for (int u = 0; u < 8; u++) {
            int id = tid + 256 * u;
            int k = id >> 5, ng = id & 31;
            float4 v = *(const float4*)&W1[k * 128 + ng * 4];
            uint4 w; w.x = f2tf(v.x); w.y = f2tf(v.y); w.z = f2tf(v.z); w.w = f2tf(v.w);
            *(uint4*)&W1u[k * SW1 + ng * 4] = w;
        }
        #pragma unroll
        for (int u = 0; u < 2; u++) {
            int id = tid + 256 * u;
            int k = id >> 2, rg = id & 3;
            float4 v = *(const float4*)&W2[k * 16 + rg * 4];
            uint4 w; w.x = f2tf(v.x); w.y = f2tf(v.y); w.z = f2tf(v.z); w.w = f2tf(v.w);
            *(uint4*)&W2u[k * SW2 + rg * 4] = w;
        }
        __syncthreads();

        const int mr = warp >> 1;
        const int nc = warp & 1;
        float acc[2][8][4];
        #pragma unroll
        for (int mt = 0; mt < 2; mt++)
            #pragma unroll
            for (int nt = 0; nt < 8; nt++)
                #pragma unroll
                for (int i = 0; i < 4; i++) acc[mt][nt][i] = 0.0f;

        #pragma unroll
        for (int kk = 0; kk < 8; kk++) {
            const int k0 = kk * 8;
            uint32_t a[2][4];
            #pragma unroll
            for (int mt = 0; mt < 2; mt++) {
                int row = mr * 32 + mt * 16;
                a[mt][0] = Hu[(row + g)     * SH + k0 + t];
                a[mt][1] = Hu[(row + g + 8) * SH + k0 + t];
                a[mt][2] = Hu[(row + g)     * SH + k0 + t + 4];
                a[mt][3] = Hu[(row + g + 8) * SH + k0 + t + 4];
            }
            #pragma unroll
            for (int nt = 0; nt < 8; nt++) {
                int n = nc * 64 + nt * 8 + g;
                uint32_t b0 = W1u[(k0 + t)     * SW1 + n];
                uint32_t b1v = W1u[(k0 + t + 4) * SW1 + n];
                mma_tf32(acc[0][nt], a[0][0], a[0][1], a[0][2], a[0][3], b0, b1v);
                mma_tf32(acc[1][nt], a[1][0], a[1][1], a[1][2], a[1][3], b0, b1v);
            }
        }
        __syncthreads();

        #pragma unroll
        for (int nt = 0; nt < 8; nt++) {
            int ncol = nc * 64 + nt * 8 + t * 2;
            float2 bb = __ldg((const float2*)&b1[ncol]);
            #pragma unroll
            for (int mt = 0; mt < 2; mt++) {
                int row = mr * 32 + mt * 16;
                float v0 = acc[mt][nt][0] + bb.x; v0 = v0 > 0.f ? v0 : 0.f;
                float v1 = acc[mt][nt][1] + bb.y; v1 = v1 > 0.f ? v1 : 0.f;
                float v2 = acc[mt][nt][2] + bb.x; v2 = v2 > 0.f ? v2 : 0.f;
                float v3 = acc[mt][nt][3] + bb.y; v3 = v3 > 0.f ? v3 : 0.f;
                uint2 w01; w01.x = f2tf(v0); w01.y = f2tf(v1);
                uint2 w23; w23.x = f2tf(v2); w23.y = f2tf(v3);
                *(uint2*)&Du[(row + g)     * SHD + ncol] = w01;
                *(uint2*)&Du[(row + g + 8) * SHD + ncol] = w23;
            }
        }
        __syncthreads();

        {
            float acc2[2][4];
            #pragma unroll
            for (int nt = 0; nt < 2; nt++)
                #pragma unroll
                for (int i = 0; i < 4; i++) acc2[nt][i] = 0.0f;

            const int rowb = warp * 16;
            #pragma unroll
            for (int kk = 0; kk < 16; kk++) {
                const int k0 = kk * 8;
                uint32_t a0 = Du[(rowb + g)     * SHD + k0 + t];
                uint32_t a1 = Du[(rowb + g + 8) * SHD + k0 + t];
                uint32_t a2 = Du[(rowb + g)     * SHD + k0 + t + 4];
                uint32_t a3 = Du[(rowb + g + 8) * SHD + k0 + t + 4];
                #pragma unroll
                for (int nt = 0; nt < 2; nt++) {
                    uint32_t b0 = W2u[(k0 + t)     * SW2 + nt * 8 + g];
                    uint32_t b1v = W2u[(k0 + t + 4) * SW2 + nt * 8 + g];
                    mma_tf32(acc2[nt], a0, a1, a2, a3, b0, b1v);
                }
            }

            #pragma unroll
            for (int nt = 0; nt < 2; nt++) {
                int r0 = nt * 8 + t * 2;
                float2 bb = __ldg((const float2*)&b2[r0]);
                int m = m0 + rowb + g;
                if (m < M_ROWS) {
                    int b = m / N_NODES, n = m - b * N_NODES;
                    float2 v; v.x = acc2[nt][0] + bb.x; v.y = acc2[nt][1] + bb.y;
                    *(float2*)((float*)outTab + ((size_t)n * 2 + b) * 16 + r0) = v;
                }
                m = m0 + rowb + g + 8;
                if (m < M_ROWS) {
                    int b = m / N_NODES, n = m - b * N_NODES;
                    float2 v; v.x = acc2[nt][2] + bb.x; v.y = acc2[nt][3] + bb.y;
                    *(float2*)((float*)outTab + ((size_t)n * 2 + b) * 16 + r0) = v;
                }
            }
        }
        __syncthreads();
    }
}

// ---------------------------------------------------------------------------
// Kernel 2: edge scoring. 128 edges/block, 256 threads.
// Swizzled stride-16 raw stage (32KB) -> 6 CTAs/SM. gamma via float4
// broadcast LDS inside the l-loop.
// ---------------------------------------------------------------------------
#define EPB 128

__global__ __launch_bounds__(256)
void edge_kernel(const int* __restrict__ eidx,
                 const float* __restrict__ gamma,
                 float* __restrict__ out)
{
    __shared__ float4 raw[EPB * 16];          // 32 KB, XOR-swizzled
    __shared__ int    sIJ[2 * EPB];
    __shared__ float  g[L_DIM * R_DIM];

    const int tid = threadIdx.x;
    const long long e0 = (long long)blockIdx.x * EPB;

    if (tid < EPB)            sIJ[tid]       = eidx[e0 + tid];
    else                      sIJ[tid + EPB - 256 + EPB] = 0; // no-op filler (tid>=EPB handled below)
    if (tid >= EPB)           sIJ[EPB + (tid - EPB)] = eidx[(size_t)E_EDGES + e0 + (tid - EPB)];
    if (tid < L_DIM * R_DIM)  g[tid] = gamma[tid];
    __syncthreads();

    // Gather: 2048 float4, 8 per thread. gid: edge = gid>>4, sub = gid&15.
    // sub: tab(1) | bb(1) | q(2). Swizzle: slot = sub ^ (edge & 15).
    {
        float4 regs[8];
        int    dsts[8];
        #pragma unroll
        for (int u = 0; u < 8; u++) {
            int gid  = tid + 256 * u;
            int edge = gid >> 4;
            int sub  = gid & 15;
            int tab  = sub >> 3;
            int k    = sub & 7;
            int node = sIJ[tab * EPB + edge];
            const float4* tbl = tab ? g_b : g_a;
            regs[u] = tbl[(size_t)node * 8 + k];
            dsts[u] = edge * 16 + (sub ^ (edge & 15));
        }
        #pragma unroll
        for (int u = 0; u < 8; u++) raw[dsts[u]] = regs[u];
    }
    __syncthreads();

    // Compute: thread -> (bb = tid>>7, e = tid&127).
    {
        const int bb = tid >> 7;
        const int e  = tid & 127;
        const int sw = e & 15;

        float p[16];
        #pragma unroll
        for (int q = 0; q < 4; q++) {
            float4 av = raw[e * 16 + ((bb * 4 + q)     ^ sw)];
            float4 bv = raw[e * 16 + ((8 + bb * 4 + q) ^ sw)];
            p[q * 4 + 0] = av.x * bv.x;
            p[q * 4 + 1] = av.y * bv.y;
            p[q * 4 + 2] = av.z * bv.z;
            p[q * 4 + 3] = av.w * bv.w;
        }

        float* o = out + (size_t)bb * L_DIM * E_EDGES + e0 + e;
        #pragma unroll
        for (int l = 0; l < L_DIM; l++) {
            const float4* gr = (const float4*)&g[l * R_DIM];
            float4 g0 = gr[0], g1 = gr[1], g2 = gr[2], g3 = gr[3];
            float s = g0.x * p[0] + g0.y * p[1] + g0.z * p[2] + g0.w * p[3]
                    + g1.x * p[4] + g1.y * p[5] + g1.z * p[6] + g1.w * p[7]
                    + g2.x * p[8] + g2.y * p[9] + g2.z * p[10] + g2.w * p[11]
                    + g3.x * p[12] + g3.y * p[13] + g3.z * p[14] + g3.w * p[15];
            o[(size_t)l * E_EDGES] = s;
        }
    }
}

// ---------------------------------------------------------------------------
// Launch
// ---------------------------------------------------------------------------
extern "C" void kernel_launch(void* const* d_in, const int* in_sizes, int n_in,
                              void* d_out, int out_size)
{
    const float* X    = (const float*)d_in[0];
    const int*   eidx = (const int*)d_in[1];
    const float* W1s  = (const float*)d_in[2];
    const float* b1s  = (const float*)d_in[3];
    const float* W2s  = (const float*)d_in[4];
    const float* b2s  = (const float*)d_in[5];
    const float* W1d  = (const float*)d_in[6];
    const float* b1d  = (const float*)d_in[7];
    const float* W2d  = (const float*)d_in[8];
    const float* b2d  = (const float*)d_in[9];
    const float* gamma= (const float*)d_in[10];
    float* out = (float*)d_out;

    const int mlp_smem = (128 * SW2 + 128 * SH + 64 * SW1) * (int)sizeof(float);
    static bool attr_done = false;
    if (!attr_done) {
        cudaFuncSetAttribute(mlp_kernel, cudaFuncAttributeMaxDynamicSharedMemorySize, mlp_smem);
        attr_done = true;
    }

    const int blocks1 = (M_ROWS + 127) / 128;
    mlp_kernel<<<blocks1, 256, mlp_smem>>>(X, W1s, b1s, W2s, b2s, W1d, b1d, W2d, b2d);

    const int blocks2 = E_EDGES / EPB;
    edge_kernel<<<blocks2, 256>>>(eidx, gamma, out);
}

// round 10
// speedup vs baseline: 1.2242x; 1.2242x over previous
#include <cuda_runtime.h>
#include <cstddef>
#include <cstdint>

#define N_NODES 50000
#define C_DIM   64
#define HID_DIM 128
#define R_DIM   16
#define B_DIM   2
#define L_DIM   12
#define E_EDGES 1600000
#define T_DIM   8
#define M_ROWS  (B_DIM * N_NODES)   // 100000

// Tables laid out [node][batch][16 floats]: one node = one 128B line.
__device__ __align__(128) float4 g_a[M_ROWS * 4];
__device__ __align__(128) float4 g_b[M_ROWS * 4];

__device__ __forceinline__ uint32_t f2tf(float x) {
    uint32_t r;
    asm("cvt.rna.tf32.f32 %0, %1;" : "=r"(r) : "f"(x));
    return r;
}

__device__ __forceinline__ void mma_tf32(float* d, uint32_t a0, uint32_t a1,
                                         uint32_t a2, uint32_t a3,
                                         uint32_t b0, uint32_t b1) {
    asm volatile(
        "mma.sync.aligned.m16n8k8.row.col.f32.tf32.tf32.f32 "
        "{%0,%1,%2,%3}, {%4,%5,%6,%7}, {%8,%9}, {%0,%1,%2,%3};"
        : "+f"(d[0]), "+f"(d[1]), "+f"(d[2]), "+f"(d[3])
        : "r"(a0), "r"(a1), "r"(a2), "r"(a3), "r"(b0), "r"(b1));
}

// ---------------------------------------------------------------------------
// Kernel 1: tf32 tensor-core MLP (unchanged from measured ~47us version).
// ---------------------------------------------------------------------------
#define SH  68
#define SW1 136
#define SHD 132
#define SW2 20

__global__ __launch_bounds__(256, 2)
void mlp_kernel(const float* __restrict__ X,
                const float* __restrict__ W1s, const float* __restrict__ b1s,
                const float* __restrict__ W2s, const float* __restrict__ b2s,
                const float* __restrict__ W1d, const float* __restrict__ b1d,
                const float* __restrict__ W2d, const float* __restrict__ b2d)
{
    extern __shared__ float sh[];
    float* W2sm = sh;                     // [128][20]
    float* Hsm  = sh + 128 * SW2;         // [128][68]
    float* W1sm = Hsm + 128 * SH;         // [64][136]
    float* Hid  = Hsm;                    // [128][132] alias

    const int tid  = threadIdx.x;
    const int lane = tid & 31;
    const int warp = tid >> 5;
    const int g    = lane >> 2;
    const int t    = lane & 3;
    const int m0   = blockIdx.x * 128;

    uint32_t* Hu  = (uint32_t*)Hsm;
    uint32_t* W1u = (uint32_t*)W1sm;
    uint32_t* W2u = (uint32_t*)W2sm;
    uint32_t* Du  = (uint32_t*)Hid;

    for (int set = 0; set < 2; set++) {
        const float* W1 = set ? W1d : W1s;
        const float* b1 = set ? b1d : b1s;
        const float* W2 = set ? W2d : W2s;
        const float* b2 = set ? b2d : b2s;
        float4* outTab  = set ? g_b : g_a;

        #pragma unroll
        for (int u = 0; u < 8; u++) {
            int id = tid + 256 * u;
            int r  = id >> 4, cg = id & 15;
            int m  = m0 + r;
            float4 v = make_float4(0.f, 0.f, 0.f, 0.f);
            if (m < M_ROWS) {
                int b = m / N_NODES;
                int n = m - b * N_NODES;
                v = *(const float4*)&X[(((size_t)b * T_DIM + (T_DIM - 1)) * N_NODES + n) * C_DIM + cg * 4];
            }
            uint4 w; w.x = f2tf(v.x); w.y = f2tf(v.y); w.z = f2tf(v.z); w.w = f2tf(v.w);
            *(uint4*)&Hu[r * SH + cg * 4] = w;
        }
        #pragma unroll
        for (int u = 0; u < 8; u++) {
            int id = tid + 256 * u;
            int k = id >> 5, ng = id & 31;
            float4 v = *(const float4*)&W1[k * 128 + ng * 4];
            uint4 w; w.x = f2tf(v.x); w.y = f2tf(v.y); w.z = f2tf(v.z); w.w = f2tf(v.w);
            *(uint4*)&W1u[k * SW1 + ng * 4] = w;
        }
        #pragma unroll
        for (int u = 0; u < 2; u++) {
            int id = tid + 256 * u;
            int k = id >> 2, rg = id & 3;
            float4 v = *(const float4*)&W2[k * 16 + rg * 4];
            uint4 w; w.x = f2tf(v.x); w.y = f2tf(v.y); w.z = f2tf(v.z); w.w = f2tf(v.w);
            *(uint4*)&W2u[k * SW2 + rg * 4] = w;
        }
        __syncthreads();

        const int mr = warp >> 1;
        const int nc = warp & 1;
        float acc[2][8][4];
        #pragma unroll
        for (int mt = 0; mt < 2; mt++)
            #pragma unroll
            for (int nt = 0; nt < 8; nt++)
                #pragma unroll
                for (int i = 0; i < 4; i++) acc[mt][nt][i] = 0.0f;

        #pragma unroll
        for (int kk = 0; kk < 8; kk++) {
            const int k0 = kk * 8;
            uint32_t a[2][4];
            #pragma unroll
            for (int mt = 0; mt < 2; mt++) {
                int row = mr * 32 + mt * 16;
                a[mt][0] = Hu[(row + g)     * SH + k0 + t];
                a[mt][1] = Hu[(row + g + 8) * SH + k0 + t];
                a[mt][2] = Hu[(row + g)     * SH + k0 + t + 4];
                a[mt][3] = Hu[(row + g + 8) * SH + k0 + t + 4];
            }
            #pragma unroll
            for (int nt = 0; nt < 8; nt++) {
                int n = nc * 64 + nt * 8 + g;
                uint32_t b0 = W1u[(k0 + t)     * SW1 + n];
                uint32_t b1v = W1u[(k0 + t + 4) * SW1 + n];
                mma_tf32(acc[0][nt], a[0][0], a[0][1], a[0][2], a[0][3], b0, b1v);
                mma_tf32(acc[1][nt], a[1][0], a[1][1], a[1][2], a[1][3], b0, b1v);
            }
        }
        __syncthreads();

        #pragma unroll
        for (int nt = 0; nt < 8; nt++) {
            int ncol = nc * 64 + nt * 8 + t * 2;
            float2 bb = __ldg((const float2*)&b1[ncol]);
            #pragma unroll
            for (int mt = 0; mt < 2; mt++) {
                int row = mr * 32 + mt * 16;
                float v0 = acc[mt][nt][0] + bb.x; v0 = v0 > 0.f ? v0 : 0.f;
                float v1 = acc[mt][nt][1] + bb.y; v1 = v1 > 0.f ? v1 : 0.f;
                float v2 = acc[mt][nt][2] + bb.x; v2 = v2 > 0.f ? v2 : 0.f;
                float v3 = acc[mt][nt][3] + bb.y; v3 = v3 > 0.f ? v3 : 0.f;
                uint2 w01; w01.x = f2tf(v0); w01.y = f2tf(v1);
                uint2 w23; w23.x = f2tf(v2); w23.y = f2tf(v3);
                *(uint2*)&Du[(row + g)     * SHD + ncol] = w01;
                *(uint2*)&Du[(row + g + 8) * SHD + ncol] = w23;
            }
        }
        __syncthreads();

        {
            float acc2[2][4];
            #pragma unroll
            for (int nt = 0; nt < 2; nt++)
                #pragma unroll
                for (int i = 0; i < 4; i++) acc2[nt][i] = 0.0f;

            const int rowb = warp * 16;
            #pragma unroll
            for (int kk = 0; kk < 16; kk++) {
                const int k0 = kk * 8;
                uint32_t a0 = Du[(rowb + g)     * SHD + k0 + t];
                uint32_t a1 = Du[(rowb + g + 8) * SHD + k0 + t];
                uint32_t a2 = Du[(rowb + g)     * SHD + k0 + t + 4];
                uint32_t a3 = Du[(rowb + g + 8) * SHD + k0 + t + 4];
                #pragma unroll
                for (int nt = 0; nt < 2; nt++) {
                    uint32_t b0 = W2u[(k0 + t)     * SW2 + nt * 8 + g];
                    uint32_t b1v = W2u[(k0 + t + 4) * SW2 + nt * 8 + g];
                    mma_tf32(acc2[nt], a0, a1, a2, a3, b0, b1v);
                }
            }

            #pragma unroll
            for (int nt = 0; nt < 2; nt++) {
                int r0 = nt * 8 + t * 2;
                float2 bb = __ldg((const float2*)&b2[r0]);
                int m = m0 + rowb + g;
                if (m < M_ROWS) {
                    int b = m / N_NODES, n = m - b * N_NODES;
                    float2 v; v.x = acc2[nt][0] + bb.x; v.y = acc2[nt][1] + bb.y;
                    *(float2*)((float*)outTab + ((size_t)n * 2 + b) * 16 + r0) = v;
                }
                m = m0 + rowb + g + 8;
                if (m < M_ROWS) {
                    int b = m / N_NODES, n = m - b * N_NODES;
                    float2 v; v.x = acc2[nt][2] + bb.x; v.y = acc2[nt][3] + bb.y;
                    *(float2*)((float*)outTab + ((size_t)n * 2 + b) * 16 + r0) = v;
                }
            }
        }
        __syncthreads();
    }
}

// ---------------------------------------------------------------------------
// Kernel 2: edge scoring with fused product-gather. 256 edges/block.
// Gather lane (edge, sub=bb*4+q) loads a-quad of I and b-quad of J,
// multiplies, stages ONLY p-quads (half the staging traffic of before).
// Stage stride = 9 float4 (conflict-free both phases). smem ~39.7KB.
// ---------------------------------------------------------------------------
#define EPB 256
#define PSTRIDE 9     // float4 per edge in p-stage (8 + 1 pad)

__global__ __launch_bounds__(256)
void edge_kernel(const int* __restrict__ eidx,
                 const float* __restrict__ gamma,
                 float* __restrict__ out)
{
    __shared__ float4 pst[EPB * PSTRIDE];    // 36,864 B
    __shared__ int    sIJ[2 * EPB];
    __shared__ float  g[L_DIM * R_DIM];

    const int tid = threadIdx.x;
    const long long e0 = (long long)blockIdx.x * EPB;

    sIJ[tid]       = eidx[e0 + tid];
    sIJ[tid + EPB] = eidx[(size_t)E_EDGES + e0 + tid];
    if (tid < L_DIM * R_DIM) g[tid] = gamma[tid];
    __syncthreads();

    // Fused gather+product: 2048 (edge,sub) pairs, 8 per thread.
    // warp = 4 consecutive edges x 8 subs -> a: 4 lines, b: 4 lines per instr.
    {
        float4 pr[8];
        int    dst[8];
        #pragma unroll
        for (int u = 0; u < 8; u++) {
            int gid  = tid + 256 * u;
            int edge = gid >> 3;
            int sub  = gid & 7;            // bb*4 + q
            int nI   = sIJ[edge];
            int nJ   = sIJ[EPB + edge];
            float4 av = g_a[(size_t)nI * 8 + sub];
            float4 bv = g_b[(size_t)nJ * 8 + sub];
            float4 p;
            p.x = av.x * bv.x; p.y = av.y * bv.y;
            p.z = av.z * bv.z; p.w = av.w * bv.w;
            pr[u]  = p;
            dst[u] = edge * PSTRIDE + sub;
        }
        #pragma unroll
        for (int u = 0; u < 8; u++) pst[dst[u]] = pr[u];
    }
    __syncthreads();

    // Compute: thread = edge, both batches. gamma loaded once per l, reused
    // for both batches.
    {
        const float4* base = pst + tid * PSTRIDE;
        float p0[16], p1[16];
        #pragma unroll
        for (int q = 0; q < 4; q++) {
            float4 v0 = base[q];
            float4 v1 = base[4 + q];
            p0[q * 4 + 0] = v0.x; p0[q * 4 + 1] = v0.y;
            p0[q * 4 + 2] = v0.z; p0[q * 4 + 3] = v0.w;
            p1[q * 4 + 0] = v1.x; p1[q * 4 + 1] = v1.y;
            p1[q * 4 + 2] = v1.z; p1[q * 4 + 3] = v1.w;
        }

        float* o0 = out + e0 + tid;
        float* o1 = out + (size_t)L_DIM * E_EDGES + e0 + tid;
        #pragma unroll
        for (int l = 0; l < L_DIM; l++) {
            const float4* gr = (const float4*)&g[l * R_DIM];
            float4 g0 = gr[0], g1 = gr[1], g2 = gr[2], g3 = gr[3];
            float s0 = g0.x * p0[0]  + g0.y * p0[1]  + g0.z * p0[2]  + g0.w * p0[3]
                     + g1.x * p0[4]  + g1.y * p0[5]  + g1.z * p0[6]  + g1.w * p0[7]
                     + g2.x * p0[8]  + g2.y * p0[9]  + g2.z * p0[10] + g2.w * p0[11]
                     + g3.x * p0[12] + g3.y * p0[13] + g3.z * p0[14] + g3.w * p0[15];
            float s1 = g0.x * p1[0]  + g0.y * p1[1]  + g0.z * p1[2]  + g0.w * p1[3]
                     + g1.x * p1[4]  + g1.y * p1[5]  + g1.z * p1[6]  + g1.w * p1[7]
                     + g2.x * p1[8]  + g2.y * p1[9]  + g2.z * p1[10] + g2.w * p1[11]
                     + g3.x * p1[12] + g3.y * p1[13] + g3.z * p1[14] + g3.w * p1[15];
            o0[(size_t)l * E_EDGES] = s0;
            o1[(size_t)l * E_EDGES] = s1;
        }
    }
}

// ---------------------------------------------------------------------------
// Launch
// ---------------------------------------------------------------------------
extern "C" void kernel_launch(void* const* d_in, const int* in_sizes, int n_in,
                              void* d_out, int out_size)
{
    const float* X    = (const float*)d_in[0];
    const int*   eidx = (const int*)d_in[1];
    const float* W1s  = (const float*)d_in[2];
    const float* b1s  = (const float*)d_in[3];
    const float* W2s  = (const float*)d_in[4];
    const float* b2s  = (const float*)d_in[5];
    const float* W1d  = (const float*)d_in[6];
    const float* b1d  = (const float*)d_in[7];
    const float* W2d  = (const float*)d_in[8];
    const float* b2d  = (const float*)d_in[9];
    const float* gamma= (const float*)d_in[10];
    float* out = (float*)d_out;

    const int mlp_smem = (128 * SW2 + 128 * SH + 64 * SW1) * (int)sizeof(float);
    static bool attr_done = false;
    if (!attr_done) {
        cudaFuncSetAttribute(mlp_kernel, cudaFuncAttributeMaxDynamicSharedMemorySize, mlp_smem);
        attr_done = true;
    }

    const int blocks1 = (M_ROWS + 127) / 128;
    mlp_kernel<<<blocks1, 256, mlp_smem>>>(X, W1s, b1s, W2s, b2s, W1d, b1d, W2d, b2d);

    const int blocks2 = E_EDGES / EPB;
    edge_kernel<<<blocks2, 256>>>(eidx, gamma, out);
}

// round 11
// speedup vs baseline: 1.2551x; 1.0252x over previous
#include <cuda_runtime.h>
#include <cstddef>
#include <cstdint>

#define N_NODES 50000
#define C_DIM   64
#define HID_DIM 128
#define R_DIM   16
#define B_DIM   2
#define L_DIM   12
#define E_EDGES 1600000
#define T_DIM   8
#define M_ROWS  (B_DIM * N_NODES)   // 100000

// Tables laid out [node][batch][16 floats]: one node = one 128B line.
__device__ __align__(128) float4 g_a[M_ROWS * 4];
__device__ __align__(128) float4 g_b[M_ROWS * 4];

__device__ __forceinline__ uint32_t f2tf(float x) {
    uint32_t r;
    asm("cvt.rna.tf32.f32 %0, %1;" : "=r"(r) : "f"(x));
    return r;
}

__device__ __forceinline__ void mma_tf32(float* d, uint32_t a0, uint32_t a1,
                                         uint32_t a2, uint32_t a3,
                                         uint32_t b0, uint32_t b1) {
    asm volatile(
        "mma.sync.aligned.m16n8k8.row.col.f32.tf32.tf32.f32 "
        "{%0,%1,%2,%3}, {%4,%5,%6,%7}, {%8,%9}, {%0,%1,%2,%3};"
        : "+f"(d[0]), "+f"(d[1]), "+f"(d[2]), "+f"(d[3])
        : "r"(a0), "r"(a1), "r"(a2), "r"(a3), "r"(b0), "r"(b1));
}

// ---------------------------------------------------------------------------
// Kernel 1: tf32 tensor-core MLP. One weight set per blockIdx.y (staging is
// conflict-free row-major, so the split is safe now). 128-row tile, 8 warps.
// ---------------------------------------------------------------------------
#define SH  68
#define SW1 136
#define SHD 132
#define SW2 20

__global__ __launch_bounds__(256, 2)
void mlp_kernel(const float* __restrict__ X,
                const float* __restrict__ W1s, const float* __restrict__ b1s,
                const float* __restrict__ W2s, const float* __restrict__ b2s,
                const float* __restrict__ W1d, const float* __restrict__ b1d,
                const float* __restrict__ W2d, const float* __restrict__ b2d)
{
    extern __shared__ float sh[];
    float* W2sm = sh;                     // [128][20]
    float* Hsm  = sh + 128 * SW2;         // [128][68]
    float* W1sm = Hsm + 128 * SH;         // [64][136]
    float* Hid  = Hsm;                    // [128][132] alias (Hsm+W1sm dead)

    const int tid  = threadIdx.x;
    const int lane = tid & 31;
    const int warp = tid >> 5;
    const int g    = lane >> 2;
    const int t    = lane & 3;
    const int m0   = blockIdx.x * 128;
    const int set  = blockIdx.y;

    const float* W1 = set ? W1d : W1s;
    const float* b1 = set ? b1d : b1s;
    const float* W2 = set ? W2d : W2s;
    const float* b2 = set ? b2d : b2s;
    float4* outTab  = set ? g_b : g_a;

    uint32_t* Hu  = (uint32_t*)Hsm;
    uint32_t* W1u = (uint32_t*)W1sm;
    uint32_t* W2u = (uint32_t*)W2sm;
    uint32_t* Du  = (uint32_t*)Hid;

    // ---- Stage H row-major [r][k] ----
    #pragma unroll
    for (int u = 0; u < 8; u++) {
        int id = tid + 256 * u;
        int r  = id >> 4, cg = id & 15;
        int m  = m0 + r;
        float4 v = make_float4(0.f, 0.f, 0.f, 0.f);
        if (m < M_ROWS) {
            int b = m / N_NODES;
            int n = m - b * N_NODES;
            v = *(const float4*)&X[(((size_t)b * T_DIM + (T_DIM - 1)) * N_NODES + n) * C_DIM + cg * 4];
        }
        uint4 w; w.x = f2tf(v.x); w.y = f2tf(v.y); w.z = f2tf(v.z); w.w = f2tf(v.w);
        *(uint4*)&Hu[r * SH + cg * 4] = w;
    }
    // ---- Stage W1 row-major [k][n] ----
    #pragma unroll
    for (int u = 0; u < 8; u++) {
        int id = tid + 256 * u;
        int k = id >> 5, ng = id & 31;
        float4 v = *(const float4*)&W1[k * 128 + ng * 4];
        uint4 w; w.x = f2tf(v.x); w.y = f2tf(v.y); w.z = f2tf(v.z); w.w = f2tf(v.w);
        *(uint4*)&W1u[k * SW1 + ng * 4] = w;
    }
    // ---- Stage W2 row-major [k][r] ----
    #pragma unroll
    for (int u = 0; u < 2; u++) {
        int id = tid + 256 * u;
        int k = id >> 2, rg = id & 3;
        float4 v = *(const float4*)&W2[k * 16 + rg * 4];
        uint4 w; w.x = f2tf(v.x); w.y = f2tf(v.y); w.z = f2tf(v.z); w.w = f2tf(v.w);
        *(uint4*)&W2u[k * SW2 + rg * 4] = w;
    }
    __syncthreads();

    // -------- Layer 1: M128 N128 K64 --------
    const int mr = warp >> 1;
    const int nc = warp & 1;
    float acc[2][8][4];
    #pragma unroll
    for (int mt = 0; mt < 2; mt++)
        #pragma unroll
        for (int nt = 0; nt < 8; nt++)
            #pragma unroll
            for (int i = 0; i < 4; i++) acc[mt][nt][i] = 0.0f;

    #pragma unroll
    for (int kk = 0; kk < 8; kk++) {
        const int k0 = kk * 8;
        uint32_t a[2][4];
        #pragma unroll
        for (int mt = 0; mt < 2; mt++) {
            int row = mr * 32 + mt * 16;
            a[mt][0] = Hu[(row + g)     * SH + k0 + t];
            a[mt][1] = Hu[(row + g + 8) * SH + k0 + t];
            a[mt][2] = Hu[(row + g)     * SH + k0 + t + 4];
            a[mt][3] = Hu[(row + g + 8) * SH + k0 + t + 4];
        }
        #pragma unroll
        for (int nt = 0; nt < 8; nt++) {
            int n = nc * 64 + nt * 8 + g;
            uint32_t b0 = W1u[(k0 + t)     * SW1 + n];
            uint32_t b1v = W1u[(k0 + t + 4) * SW1 + n];
            mma_tf32(acc[0][nt], a[0][0], a[0][1], a[0][2], a[0][3], b0, b1v);
            mma_tf32(acc[1][nt], a[1][0], a[1][1], a[1][2], a[1][3], b0, b1v);
        }
    }
    __syncthreads();   // Hsm/W1sm dead -> Hid may overwrite

    // bias + relu -> Hid
    #pragma unroll
    for (int nt = 0; nt < 8; nt++) {
        int ncol = nc * 64 + nt * 8 + t * 2;
        float2 bb = __ldg((const float2*)&b1[ncol]);
        #pragma unroll
        for (int mt = 0; mt < 2; mt++) {
            int row = mr * 32 + mt * 16;
            float v0 = acc[mt][nt][0] + bb.x; v0 = v0 > 0.f ? v0 : 0.f;
            float v1 = acc[mt][nt][1] + bb.y; v1 = v1 > 0.f ? v1 : 0.f;
            float v2 = acc[mt][nt][2] + bb.x; v2 = v2 > 0.f ? v2 : 0.f;
            float v3 = acc[mt][nt][3] + bb.y; v3 = v3 > 0.f ? v3 : 0.f;
            uint2 w01; w01.x = f2tf(v0); w01.y = f2tf(v1);
            uint2 w23; w23.x = f2tf(v2); w23.y = f2tf(v3);
            *(uint2*)&Du[(row + g)     * SHD + ncol] = w01;
            *(uint2*)&Du[(row + g + 8) * SHD + ncol] = w23;
        }
    }
    __syncthreads();

    // -------- Layer 2: M128 N16 K128 --------
    {
        float acc2[2][4];
        #pragma unroll
        for (int nt = 0; nt < 2; nt++)
            #pragma unroll
            for (int i = 0; i < 4; i++) acc2[nt][i] = 0.0f;

        const int rowb = warp * 16;
        #pragma unroll
        for (int kk = 0; kk < 16; kk++) {
            const int k0 = kk * 8;
            uint32_t a0 = Du[(rowb + g)     * SHD + k0 + t];
            uint32_t a1 = Du[(rowb + g + 8) * SHD + k0 + t];
            uint32_t a2 = Du[(rowb + g)     * SHD + k0 + t + 4];
            uint32_t a3 = Du[(rowb + g + 8) * SHD + k0 + t + 4];
            #pragma unroll
            for (int nt = 0; nt < 2; nt++) {
                uint32_t b0 = W2u[(k0 + t)     * SW2 + nt * 8 + g];
                uint32_t b1v = W2u[(k0 + t + 4) * SW2 + nt * 8 + g];
                mma_tf32(acc2[nt], a0, a1, a2, a3, b0, b1v);
            }
        }

        #pragma unroll
        for (int nt = 0; nt < 2; nt++) {
            int r0 = nt * 8 + t * 2;
            float2 bb = __ldg((const float2*)&b2[r0]);
            int m = m0 + rowb + g;
            if (m < M_ROWS) {
                int b = m / N_NODES, n = m - b * N_NODES;
                float2 v; v.x = acc2[nt][0] + bb.x; v.y = acc2[nt][1] + bb.y;
                *(float2*)((float*)outTab + ((size_t)n * 2 + b) * 16 + r0) = v;
            }
            m = m0 + rowb + g + 8;
            if (m < M_ROWS) {
                int b = m / N_NODES, n = m - b * N_NODES;
                float2 v; v.x = acc2[nt][2] + bb.x; v.y = acc2[nt][3] + bb.y;
                *(float2*)((float*)outTab + ((size_t)n * 2 + b) * 16 + r0) = v;
            }
        }
    }
}

// ---------------------------------------------------------------------------
// Kernel 2: edge scoring with fused product-gather (measured 62.7us) plus
// streaming stores (.cs) so the 153MB output doesn't evict the 25.6MB node
// tables from L2.
// ---------------------------------------------------------------------------
#define EPB 256
#define PSTRIDE 9     // float4 per edge in p-stage (8 + 1 pad)

__global__ __launch_bounds__(256)
void edge_kernel(const int* __restrict__ eidx,
                 const float* __restrict__ gamma,
                 float* __restrict__ out)
{
    __shared__ float4 pst[EPB * PSTRIDE];    // 36,864 B
    __shared__ int    sIJ[2 * EPB];
    __shared__ float  g[L_DIM * R_DIM];

    const int tid = threadIdx.x;
    const long long e0 = (long long)blockIdx.x * EPB;

    sIJ[tid]       = eidx[e0 + tid];
    sIJ[tid + EPB] = eidx[(size_t)E_EDGES + e0 + tid];
    if (tid < L_DIM * R_DIM) g[tid] = gamma[tid];
    __syncthreads();

    // Fused gather+product: 2048 (edge,sub) pairs, 8 per thread.
    {
        float4 pr[8];
        int    dst[8];
        #pragma unroll
        for (int u = 0; u < 8; u++) {
            int gid  = tid + 256 * u;
            int edge = gid >> 3;
            int sub  = gid & 7;            // bb*4 + q
            int nI   = sIJ[edge];
            int nJ   = sIJ[EPB + edge];
            float4 av = g_a[(size_t)nI * 8 + sub];
            float4 bv = g_b[(size_t)nJ * 8 + sub];
            float4 p;
            p.x = av.x * bv.x; p.y = av.y * bv.y;
            p.z = av.z * bv.z; p.w = av.w * bv.w;
            pr[u]  = p;
            dst[u] = edge * PSTRIDE + sub;
        }
        #pragma unroll
        for (int u = 0; u < 8; u++) pst[dst[u]] = pr[u];
    }
    __syncthreads();

    // Compute: thread = edge, both batches; streaming stores.
    {
        const float4* base = pst + tid * PSTRIDE;
        float p0[16], p1[16];
        #pragma unroll
        for (int q = 0; q < 4; q++) {
            float4 v0 = base[q];
            float4 v1 = base[4 + q];
            p0[q * 4 + 0] = v0.x; p0[q * 4 + 1] = v0.y;
            p0[q * 4 + 2] = v0.z; p0[q * 4 + 3] = v0.w;
            p1[q * 4 + 0] = v1.x; p1[q * 4 + 1] = v1.y;
            p1[q * 4 + 2] = v1.z; p1[q * 4 + 3] = v1.w;
        }

        float* o0 = out + e0 + tid;
        float* o1 = out + (size_t)L_DIM * E_EDGES + e0 + tid;
        #pragma unroll
        for (int l = 0; l < L_DIM; l++) {
            const float4* gr = (const float4*)&g[l * R_DIM];
            float4 g0 = gr[0], g1 = gr[1], g2 = gr[2], g3 = gr[3];
            float s0 = g0.x * p0[0]  + g0.y * p0[1]  + g0.z * p0[2]  + g0.w * p0[3]
                     + g1.x * p0[4]  + g1.y * p0[5]  + g1.z * p0[6]  + g1.w * p0[7]
                     + g2.x * p0[8]  + g2.y * p0[9]  + g2.z * p0[10] + g2.w * p0[11]
                     + g3.x * p0[12] + g3.y * p0[13] + g3.z * p0[14] + g3.w * p0[15];
            float s1 = g0.x * p1[0]  + g0.y * p1[1]  + g0.z * p1[2]  + g0.w * p1[3]
                     + g1.x * p1[4]  + g1.y * p1[5]  + g1.z * p1[6]  + g1.w * p1[7]
                     + g2.x * p1[8]  + g2.y * p1[9]  + g2.z * p1[10] + g2.w * p1[11]
                     + g3.x * p1[12] + g3.y * p1[13] + g3.z * p1[14] + g3.w * p1[15];
            __stcs(o0 + (size_t)l * E_EDGES, s0);
            __stcs(o1 + (size_t)l * E_EDGES, s1);
        }
    }
}

// ---------------------------------------------------------------------------
// Launch
// ---------------------------------------------------------------------------
extern "C" void kernel_launch(void* const* d_in, const int* in_sizes, int n_in,
                              void* d_out, int out_size)
{
    const float* X    = (const float*)d_in[0];
    const int*   eidx = (const int*)d_in[1];
    const float* W1s  = (const float*)d_in[2];
    const float* b1s  = (const float*)d_in[3];
    const float* W2s  = (const float*)d_in[4];
    const float* b2s  = (const float*)d_in[5];
    const float* W1d  = (const float*)d_in[6];
    const float* b1d  = (const float*)d_in[7];
    const float* W2d  = (const float*)d_in[8];
    const float* b2d  = (const float*)d_in[9];
    const float* gamma= (const float*)d_in[10];
    float* out = (float*)d_out;

    const int mlp_smem = (128 * SW2 + 128 * SH + 64 * SW1) * (int)sizeof(float);
    static bool attr_done = false;
    if (!attr_done) {
        cudaFuncSetAttribute(mlp_kernel, cudaFuncAttributeMaxDynamicSharedMemorySize, mlp_smem);
        attr_done = true;
    }

    dim3 grid1((M_ROWS + 127) / 128, 2, 1);
    mlp_kernel<<<grid1, 256, mlp_smem>>>(X, W1s, b1s, W2s, b2s, W1d, b1d, W2d, b2d);

    const int blocks2 = E_EDGES / EPB;
    edge_kernel<<<blocks2, 256>>>(eidx, gamma, out);
}